// round 1
// baseline (speedup 1.0000x reference)
#include <cuda_runtime.h>
#include <math.h>

// Problem constants (match reference)
#define N_USERS   100000
#define N_ENTITYS 1000000
#define K_DIM     64
#define B_SZ      2048
#define DEG       32
#define N0        (B_SZ * DEG)   // 65536

// Scratch for hop-0 aggregates: [N0, K_DIM] f32 = 16 MB
__device__ float g_agg0[N0 * K_DIM];

// ---------------------------------------------------------------------------
// Warp-wide sum reduction of 4 independent values (butterfly).
// After this, all lanes hold the full sums.
// ---------------------------------------------------------------------------
__device__ __forceinline__ void warp_reduce4(float& a, float& b, float& c, float& d) {
#pragma unroll
    for (int off = 16; off > 0; off >>= 1) {
        a += __shfl_xor_sync(0xFFFFFFFFu, a, off);
        b += __shfl_xor_sync(0xFFFFFFFFu, b, off);
        c += __shfl_xor_sync(0xFFFFFFFFu, c, off);
        d += __shfl_xor_sync(0xFFFFFFFFu, d, off);
    }
}

__device__ __forceinline__ void warp_reduce2(float& a, float& b) {
#pragma unroll
    for (int off = 16; off > 0; off >>= 1) {
        a += __shfl_xor_sync(0xFFFFFFFFu, a, off);
        b += __shfl_xor_sync(0xFFFFFFFFu, b, off);
    }
}

__device__ __forceinline__ float renorm_scale(float sumsq) {
    // scale = min(1, 1 / max(sqrt(ss), 1e-12))
    float n = sqrtf(sumsq);
    return fminf(1.0f, 1.0f / fmaxf(n, 1e-12f));
}

// ---------------------------------------------------------------------------
// Hop 0: one warp per node i in [0, N0).
//   agg0[i] = fm(renorm(entity_emb[nbr0[i,:]])) + renorm(entity_emb[node_ids0[i]])
// Lane l owns dims {2l, 2l+1}: a 256B row = 2 coalesced 128B transactions.
// ---------------------------------------------------------------------------
__global__ void __launch_bounds__(256) hop0_kernel(
    const float* __restrict__ entity_emb,
    const int*   __restrict__ node_ids0,
    const int*   __restrict__ nbr0)
{
    const int warp = (blockIdx.x * blockDim.x + threadIdx.x) >> 5;
    const int lane = threadIdx.x & 31;
    if (warp >= N0) return;

    // Each lane holds one neighbor index (coalesced 128B load of the index row)
    const int my_nbr = nbr0[warp * DEG + lane];

    float sx = 0.f, sy = 0.f;   // FM: sum over neighbors, per-dim
    float qx = 0.f, qy = 0.f;   // FM: sum of squares over neighbors, per-dim

#pragma unroll
    for (int j0 = 0; j0 < DEG; j0 += 4) {
        // Broadcast 4 row indices, issue 4 independent gathers (MLP=4)
        const int i0 = __shfl_sync(0xFFFFFFFFu, my_nbr, j0 + 0);
        const int i1 = __shfl_sync(0xFFFFFFFFu, my_nbr, j0 + 1);
        const int i2 = __shfl_sync(0xFFFFFFFFu, my_nbr, j0 + 2);
        const int i3 = __shfl_sync(0xFFFFFFFFu, my_nbr, j0 + 3);

        const float2 v0 = *(const float2*)(entity_emb + (size_t)i0 * K_DIM + lane * 2);
        const float2 v1 = *(const float2*)(entity_emb + (size_t)i1 * K_DIM + lane * 2);
        const float2 v2 = *(const float2*)(entity_emb + (size_t)i2 * K_DIM + lane * 2);
        const float2 v3 = *(const float2*)(entity_emb + (size_t)i3 * K_DIM + lane * 2);

        float p0 = v0.x * v0.x + v0.y * v0.y;
        float p1 = v1.x * v1.x + v1.y * v1.y;
        float p2 = v2.x * v2.x + v2.y * v2.y;
        float p3 = v3.x * v3.x + v3.y * v3.y;
        warp_reduce4(p0, p1, p2, p3);

        const float s0 = renorm_scale(p0);
        const float s1 = renorm_scale(p1);
        const float s2 = renorm_scale(p2);
        const float s3 = renorm_scale(p3);

        float wx, wy;
        wx = v0.x * s0; wy = v0.y * s0; sx += wx; sy += wy; qx += wx * wx; qy += wy * wy;
        wx = v1.x * s1; wy = v1.y * s1; sx += wx; sy += wy; qx += wx * wx; qy += wy * wy;
        wx = v2.x * s2; wy = v2.y * s2; sx += wx; sy += wy; qx += wx * wx; qy += wy * wy;
        wx = v3.x * s3; wy = v3.y * s3; sx += wx; sy += wy; qx += wx * wx; qy += wy * wy;
    }

    // Target row (renormed)
    const int tgt_idx = node_ids0[warp];
    const float2 tv = *(const float2*)(entity_emb + (size_t)tgt_idx * K_DIM + lane * 2);
    float tp = tv.x * tv.x + tv.y * tv.y;
    float dummy = 0.f;
    warp_reduce2(tp, dummy);
    const float ts = renorm_scale(tp);

    // att == 1 (softmax over singleton axis) => agg0 = fm + tgt
    float2 outv;
    outv.x = sx * sx - qx + tv.x * ts;
    outv.y = sy * sy - qy + tv.y * ts;
    *(float2*)(g_agg0 + (size_t)warp * K_DIM + lane * 2) = outv;
}

// ---------------------------------------------------------------------------
// Hop 1 + score: one warp per b in [0, B).
//   ent1 = agg0[nbr1_idx[b,:]]  (NO renorm — these are aggregates)
//   items = fm(ent1) + renorm(entity_emb[item_ids[b]])
//   logit[b] = sigmoid( dot(renorm(user_emb[u[b]]), items) )
// ---------------------------------------------------------------------------
__global__ void __launch_bounds__(256) hop1_kernel(
    const float* __restrict__ entity_emb,
    const float* __restrict__ user_emb,
    const int*   __restrict__ u,
    const int*   __restrict__ item_ids,
    const int*   __restrict__ nbr1_idx,
    float*       __restrict__ out)
{
    const int warp = (blockIdx.x * blockDim.x + threadIdx.x) >> 5;
    const int lane = threadIdx.x & 31;
    if (warp >= B_SZ) return;

    const int my_nbr = nbr1_idx[warp * DEG + lane];

    float sx = 0.f, sy = 0.f, qx = 0.f, qy = 0.f;

#pragma unroll
    for (int j0 = 0; j0 < DEG; j0 += 4) {
        const int i0 = __shfl_sync(0xFFFFFFFFu, my_nbr, j0 + 0);
        const int i1 = __shfl_sync(0xFFFFFFFFu, my_nbr, j0 + 1);
        const int i2 = __shfl_sync(0xFFFFFFFFu, my_nbr, j0 + 2);
        const int i3 = __shfl_sync(0xFFFFFFFFu, my_nbr, j0 + 3);

        const float2 v0 = *(const float2*)(g_agg0 + (size_t)i0 * K_DIM + lane * 2);
        const float2 v1 = *(const float2*)(g_agg0 + (size_t)i1 * K_DIM + lane * 2);
        const float2 v2 = *(const float2*)(g_agg0 + (size_t)i2 * K_DIM + lane * 2);
        const float2 v3 = *(const float2*)(g_agg0 + (size_t)i3 * K_DIM + lane * 2);

        sx += v0.x + v1.x + v2.x + v3.x;
        sy += v0.y + v1.y + v2.y + v3.y;
        qx += v0.x * v0.x + v1.x * v1.x + v2.x * v2.x + v3.x * v3.x;
        qy += v0.y * v0.y + v1.y * v1.y + v2.y * v2.y + v3.y * v3.y;
    }

    // FM aggregate
    float ax = sx * sx - qx;
    float ay = sy * sy - qy;

    // Target item row (renormed) and user row (renormed) — two reductions fused
    const int it = item_ids[warp];
    const int uu = u[warp];
    const float2 tv = *(const float2*)(entity_emb + (size_t)it * K_DIM + lane * 2);
    const float2 uv = *(const float2*)(user_emb  + (size_t)uu * K_DIM + lane * 2);

    float tp = tv.x * tv.x + tv.y * tv.y;
    float up = uv.x * uv.x + uv.y * uv.y;
    warp_reduce2(tp, up);
    const float ts = renorm_scale(tp);
    const float us = renorm_scale(up);

    // items = agg1 + tgt (att == 1); dot with user
    const float ix = ax + tv.x * ts;
    const float iy = ay + tv.y * ts;
    float d = (uv.x * us) * ix + (uv.y * us) * iy;
    float d2 = 0.f;
    warp_reduce2(d, d2);

    if (lane == 0)
        out[warp] = 1.0f / (1.0f + expf(-d));
}

// ---------------------------------------------------------------------------
// Launch
// Input order (metadata): 0 entity_emb, 1 user_emb, 2 Wa, 3 ba, 4 Wh, 5 bh,
//                         6 u, 7 item_ids, 8 nbr1_idx, 9 node_ids0, 10 nbr0
// Wa/ba/Wh/bh are provably dead (softmax over singleton axis == 1).
// ---------------------------------------------------------------------------
extern "C" void kernel_launch(void* const* d_in, const int* in_sizes, int n_in,
                              void* d_out, int out_size)
{
    const float* entity_emb = (const float*)d_in[0];
    const float* user_emb   = (const float*)d_in[1];
    const int*   u          = (const int*)d_in[6];
    const int*   item_ids   = (const int*)d_in[7];
    const int*   nbr1_idx   = (const int*)d_in[8];
    const int*   node_ids0  = (const int*)d_in[9];
    const int*   nbr0       = (const int*)d_in[10];
    float* out = (float*)d_out;

    // hop0: N0 warps, 8 warps per 256-thread block
    hop0_kernel<<<N0 / 8, 256>>>(entity_emb, node_ids0, nbr0);
    // hop1: B warps
    hop1_kernel<<<B_SZ / 8, 256>>>(entity_emb, user_emb, u, item_ids, nbr1_idx, out);
}

// round 2
// speedup vs baseline: 1.4713x; 1.4713x over previous
#include <cuda_runtime.h>
#include <math.h>

// Problem constants (match reference)
#define N_USERS   100000
#define N_ENTITYS 1000000
#define K_DIM     64
#define B_SZ      2048
#define DEG       32
#define N0        (B_SZ * DEG)   // 65536

// Scratch for hop-0 aggregates: [N0, K_DIM] f32 = 16 MB
__device__ float g_agg0[N0 * K_DIM];

// ---------------------------------------------------------------------------
// Helpers
// ---------------------------------------------------------------------------
__device__ __forceinline__ float dot4(const float4& v) {
    return v.x * v.x + v.y * v.y + v.z * v.z + v.w * v.w;
}

// Reduce a value across each 16-lane half of the warp (xor 8,4,2,1).
// Two independent values reduced together to pipeline the shuffle chain.
__device__ __forceinline__ void half_reduce2(float& a, float& b) {
#pragma unroll
    for (int off = 8; off > 0; off >>= 1) {
        a += __shfl_xor_sync(0xFFFFFFFFu, a, off);
        b += __shfl_xor_sync(0xFFFFFFFFu, b, off);
    }
}

__device__ __forceinline__ float renorm_scale(float sumsq) {
    // reference: min(1, 1/max(sqrt(ss), 1e-12)) == min(1, rsqrt(max(ss, 1e-24)))
    return fminf(1.0f, rsqrtf(fmaxf(sumsq, 1e-24f)));
}

// ---------------------------------------------------------------------------
// Hop 0: one warp per node i in [0, N0).
//   agg0[i] = fm(renorm(entity_emb[nbr0[i,:]])) + renorm(entity_emb[node_ids0[i]])
// Layout: lane owns 4 dims (lane&15)*4; lanes [0,16) process even rows of the
// pair, lanes [16,32) odd rows. Each LDG.128 step reads 2 full rows (512B,
// 4x128B coalesced lines).
// ---------------------------------------------------------------------------
__global__ void __launch_bounds__(256) hop0_kernel(
    const float* __restrict__ entity_emb,
    const int*   __restrict__ node_ids0,
    const int*   __restrict__ nbr0)
{
    const int warp = (blockIdx.x * blockDim.x + threadIdx.x) >> 5;
    const int lane = threadIdx.x & 31;
    if (warp >= N0) return;

    const bool hi  = (lane >= 16);
    const int  dof = (lane & 15) * 4;          // dim offset this lane owns

    // Each lane holds one neighbor index (coalesced index load)
    const int my_nbr = nbr0[warp * DEG + lane];

    float4 sv = make_float4(0.f, 0.f, 0.f, 0.f);  // sum of renormed rows
    float4 qv = make_float4(0.f, 0.f, 0.f, 0.f);  // sum of squares

#pragma unroll
    for (int j0 = 0; j0 < DEG; j0 += 4) {
        // Broadcast 4 row indices; each half-warp takes its row of the pair.
        const int ia = __shfl_sync(0xFFFFFFFFu, my_nbr, j0 + 0);
        const int ib = __shfl_sync(0xFFFFFFFFu, my_nbr, j0 + 1);
        const int ic = __shfl_sync(0xFFFFFFFFu, my_nbr, j0 + 2);
        const int id = __shfl_sync(0xFFFFFFFFu, my_nbr, j0 + 3);
        const int idx0 = hi ? ib : ia;
        const int idx1 = hi ? id : ic;

        const float4 v0 = *(const float4*)(entity_emb + (size_t)idx0 * K_DIM + dof);
        const float4 v1 = *(const float4*)(entity_emb + (size_t)idx1 * K_DIM + dof);

        float p0 = dot4(v0);
        float p1 = dot4(v1);
        half_reduce2(p0, p1);               // per-row sumsq (within 16-lane half)

        const float s0 = renorm_scale(p0);
        const float s1 = renorm_scale(p1);

        float w;
        w = v0.x * s0; sv.x += w; qv.x += w * w;
        w = v0.y * s0; sv.y += w; qv.y += w * w;
        w = v0.z * s0; sv.z += w; qv.z += w * w;
        w = v0.w * s0; sv.w += w; qv.w += w * w;
        w = v1.x * s1; sv.x += w; qv.x += w * w;
        w = v1.y * s1; sv.y += w; qv.y += w * w;
        w = v1.z * s1; sv.z += w; qv.z += w * w;
        w = v1.w * s1; sv.w += w; qv.w += w * w;
    }

    // Combine the two halves (each half saw 16 of the 32 rows).
    sv.x += __shfl_xor_sync(0xFFFFFFFFu, sv.x, 16);
    sv.y += __shfl_xor_sync(0xFFFFFFFFu, sv.y, 16);
    sv.z += __shfl_xor_sync(0xFFFFFFFFu, sv.z, 16);
    sv.w += __shfl_xor_sync(0xFFFFFFFFu, sv.w, 16);
    qv.x += __shfl_xor_sync(0xFFFFFFFFu, qv.x, 16);
    qv.y += __shfl_xor_sync(0xFFFFFFFFu, qv.y, 16);
    qv.z += __shfl_xor_sync(0xFFFFFFFFu, qv.z, 16);
    qv.w += __shfl_xor_sync(0xFFFFFFFFu, qv.w, 16);

    // Target row (renormed). Both halves load/compute identically.
    const int tgt_idx = node_ids0[warp];
    const float4 tv = *(const float4*)(entity_emb + (size_t)tgt_idx * K_DIM + dof);
    float tp = tv.x * tv.x + tv.y * tv.y + tv.z * tv.z + tv.w * tv.w;
    float dm = 0.f;
    half_reduce2(tp, dm);
    const float ts = renorm_scale(tp);

    // att == 1 (softmax over singleton axis) => agg0 = (s^2 - q) + tgt
    float4 outv;
    outv.x = sv.x * sv.x - qv.x + tv.x * ts;
    outv.y = sv.y * sv.y - qv.y + tv.y * ts;
    outv.z = sv.z * sv.z - qv.z + tv.z * ts;
    outv.w = sv.w * sv.w - qv.w + tv.w * ts;

    if (!hi)
        *(float4*)(g_agg0 + (size_t)warp * K_DIM + dof) = outv;
}

// ---------------------------------------------------------------------------
// Hop 1 + score: one warp per b in [0, B).
//   ent1 = agg0[nbr1_idx[b,:]]  (NO renorm — these are aggregates)
//   items = fm(ent1) + renorm(entity_emb[item_ids[b]])
//   logit[b] = sigmoid( dot(renorm(user_emb[u[b]]), items) )
// ---------------------------------------------------------------------------
__global__ void __launch_bounds__(128) hop1_kernel(
    const float* __restrict__ entity_emb,
    const float* __restrict__ user_emb,
    const int*   __restrict__ u,
    const int*   __restrict__ item_ids,
    const int*   __restrict__ nbr1_idx,
    float*       __restrict__ out)
{
    const int warp = (blockIdx.x * blockDim.x + threadIdx.x) >> 5;
    const int lane = threadIdx.x & 31;
    if (warp >= B_SZ) return;

    const bool hi  = (lane >= 16);
    const int  dof = (lane & 15) * 4;

    const int my_nbr = nbr1_idx[warp * DEG + lane];

    float4 sv = make_float4(0.f, 0.f, 0.f, 0.f);
    float4 qv = make_float4(0.f, 0.f, 0.f, 0.f);

#pragma unroll
    for (int j0 = 0; j0 < DEG; j0 += 4) {
        const int ia = __shfl_sync(0xFFFFFFFFu, my_nbr, j0 + 0);
        const int ib = __shfl_sync(0xFFFFFFFFu, my_nbr, j0 + 1);
        const int ic = __shfl_sync(0xFFFFFFFFu, my_nbr, j0 + 2);
        const int id = __shfl_sync(0xFFFFFFFFu, my_nbr, j0 + 3);
        const int idx0 = hi ? ib : ia;
        const int idx1 = hi ? id : ic;

        const float4 v0 = *(const float4*)(g_agg0 + (size_t)idx0 * K_DIM + dof);
        const float4 v1 = *(const float4*)(g_agg0 + (size_t)idx1 * K_DIM + dof);

        sv.x += v0.x + v1.x;  qv.x += v0.x * v0.x + v1.x * v1.x;
        sv.y += v0.y + v1.y;  qv.y += v0.y * v0.y + v1.y * v1.y;
        sv.z += v0.z + v1.z;  qv.z += v0.z * v0.z + v1.z * v1.z;
        sv.w += v0.w + v1.w;  qv.w += v0.w * v0.w + v1.w * v1.w;
    }

    // Combine halves
    sv.x += __shfl_xor_sync(0xFFFFFFFFu, sv.x, 16);
    sv.y += __shfl_xor_sync(0xFFFFFFFFu, sv.y, 16);
    sv.z += __shfl_xor_sync(0xFFFFFFFFu, sv.z, 16);
    sv.w += __shfl_xor_sync(0xFFFFFFFFu, sv.w, 16);
    qv.x += __shfl_xor_sync(0xFFFFFFFFu, qv.x, 16);
    qv.y += __shfl_xor_sync(0xFFFFFFFFu, qv.y, 16);
    qv.z += __shfl_xor_sync(0xFFFFFFFFu, qv.z, 16);
    qv.w += __shfl_xor_sync(0xFFFFFFFFu, qv.w, 16);

    // Item row + user row, renormed (both halves compute identically)
    const int it = item_ids[warp];
    const int uu = u[warp];
    const float4 tv = *(const float4*)(entity_emb + (size_t)it * K_DIM + dof);
    const float4 uv = *(const float4*)(user_emb  + (size_t)uu * K_DIM + dof);

    float tp = dot4(tv);
    float up = dot4(uv);
    half_reduce2(tp, up);
    const float ts = renorm_scale(tp);
    const float us = renorm_scale(up);

    // items = fm + tgt; dot with renormed user.
    // Each 16-lane half covers all 16 dim-groups, so reduce within a half.
    float d =
        (uv.x * us) * (sv.x * sv.x - qv.x + tv.x * ts) +
        (uv.y * us) * (sv.y * sv.y - qv.y + tv.y * ts) +
        (uv.z * us) * (sv.z * sv.z - qv.z + tv.z * ts) +
        (uv.w * us) * (sv.w * sv.w - qv.w + tv.w * ts);
    float dm = 0.f;
    half_reduce2(d, dm);

    if (lane == 0)
        out[warp] = 1.0f / (1.0f + expf(-d));
}

// ---------------------------------------------------------------------------
// Launch
// Input order (metadata): 0 entity_emb, 1 user_emb, 2 Wa, 3 ba, 4 Wh, 5 bh,
//                         6 u, 7 item_ids, 8 nbr1_idx, 9 node_ids0, 10 nbr0
// Wa/ba/Wh/bh are provably dead (softmax over singleton axis == 1).
// ---------------------------------------------------------------------------
extern "C" void kernel_launch(void* const* d_in, const int* in_sizes, int n_in,
                              void* d_out, int out_size)
{
    const float* entity_emb = (const float*)d_in[0];
    const float* user_emb   = (const float*)d_in[1];
    const int*   u          = (const int*)d_in[6];
    const int*   item_ids   = (const int*)d_in[7];
    const int*   nbr1_idx   = (const int*)d_in[8];
    const int*   node_ids0  = (const int*)d_in[9];
    const int*   nbr0       = (const int*)d_in[10];
    float* out = (float*)d_out;

    // hop0: N0 warps, 8 warps per 256-thread block
    hop0_kernel<<<N0 / 8, 256>>>(entity_emb, node_ids0, nbr0);
    // hop1: B warps, 4 warps per 128-thread block (512 blocks for SM spread)
    hop1_kernel<<<B_SZ / 4, 128>>>(entity_emb, user_emb, u, item_ids, nbr1_idx, out);
}

// round 5
// speedup vs baseline: 1.6686x; 1.1341x over previous
#include <cuda_runtime.h>
#include <math.h>

// Problem constants (match reference)
#define N_USERS   100000
#define N_ENTITYS 1000000
#define K_DIM     64
#define B_SZ      2048
#define DEG       32
#define N0        (B_SZ * DEG)   // 65536

// Scratch for hop-0 aggregates: [N0, K_DIM] f32 = 16 MB
__device__ float g_agg0[N0 * K_DIM];

// ---------------------------------------------------------------------------
// Helpers
// ---------------------------------------------------------------------------
__device__ __forceinline__ float dot4(const float4& v) {
    return v.x * v.x + v.y * v.y + v.z * v.z + v.w * v.w;
}

// Reduce 4 independent values across each 16-lane half (xor 8,4,2,1),
// interleaved so SHFL latency pipelines across the chains.
__device__ __forceinline__ void half_reduce4(float& a, float& b, float& c, float& d) {
#pragma unroll
    for (int off = 8; off > 0; off >>= 1) {
        a += __shfl_xor_sync(0xFFFFFFFFu, a, off);
        b += __shfl_xor_sync(0xFFFFFFFFu, b, off);
        c += __shfl_xor_sync(0xFFFFFFFFu, c, off);
        d += __shfl_xor_sync(0xFFFFFFFFu, d, off);
    }
}

__device__ __forceinline__ void half_reduce2(float& a, float& b) {
#pragma unroll
    for (int off = 8; off > 0; off >>= 1) {
        a += __shfl_xor_sync(0xFFFFFFFFu, a, off);
        b += __shfl_xor_sync(0xFFFFFFFFu, b, off);
    }
}

__device__ __forceinline__ float renorm_scale(float sumsq) {
    // reference: min(1, 1/max(sqrt(ss), 1e-12)) == min(1, rsqrt(max(ss, 1e-24)))
    return fminf(1.0f, rsqrtf(fmaxf(sumsq, 1e-24f)));
}

// Process a batch of 4 prefetched rows: per-row renorm then FM accumulate.
__device__ __forceinline__ void fm_accum4(const float4* v, float4& sv, float4& qv) {
    float p0 = dot4(v[0]);
    float p1 = dot4(v[1]);
    float p2 = dot4(v[2]);
    float p3 = dot4(v[3]);
    half_reduce4(p0, p1, p2, p3);

    const float s0 = renorm_scale(p0);
    const float s1 = renorm_scale(p1);
    const float s2 = renorm_scale(p2);
    const float s3 = renorm_scale(p3);

    float w;
    w = v[0].x * s0; sv.x += w; qv.x += w * w;
    w = v[0].y * s0; sv.y += w; qv.y += w * w;
    w = v[0].z * s0; sv.z += w; qv.z += w * w;
    w = v[0].w * s0; sv.w += w; qv.w += w * w;
    w = v[1].x * s1; sv.x += w; qv.x += w * w;
    w = v[1].y * s1; sv.y += w; qv.y += w * w;
    w = v[1].z * s1; sv.z += w; qv.z += w * w;
    w = v[1].w * s1; sv.w += w; qv.w += w * w;
    w = v[2].x * s2; sv.x += w; qv.x += w * w;
    w = v[2].y * s2; sv.y += w; qv.y += w * w;
    w = v[2].z * s2; sv.z += w; qv.z += w * w;
    w = v[2].w * s2; sv.w += w; qv.w += w * w;
    w = v[3].x * s3; sv.x += w; qv.x += w * w;
    w = v[3].y * s3; sv.y += w; qv.y += w * w;
    w = v[3].z * s3; sv.z += w; qv.z += w * w;
    w = v[3].w * s3; sv.w += w; qv.w += w * w;
}

// ---------------------------------------------------------------------------
// Hop 0: one warp per node i in [0, N0).
//   agg0[i] = fm(renorm(entity_emb[nbr0[i,:]])) + renorm(entity_emb[node_ids0[i]])
// Layout: lane owns dims (lane&15)*4 .. +3; lanes [0,16) take even rows of each
// pair, lanes [16,32) odd rows. Gather loads are software-prefetched in
// batches of 8 (MLP>=8 per warp) ahead of the reduce chains.
// ---------------------------------------------------------------------------
__global__ void __launch_bounds__(128) hop0_kernel(
    const float* __restrict__ entity_emb,
    const int*   __restrict__ node_ids0,
    const int*   __restrict__ nbr0)
{
    const int warp = (blockIdx.x * blockDim.x + threadIdx.x) >> 5;
    const int lane = threadIdx.x & 31;
    if (warp >= N0) return;

    const bool hi  = (lane >= 16);
    const int  dof = (lane & 15) * 4;          // dim offset this lane owns

    // Each lane holds one neighbor index (coalesced index load)
    const int my_nbr  = nbr0[warp * DEG + lane];
    const int tgt_idx = node_ids0[warp];

    // Target row load issued first (longest to consumption)
    const float4 tv = *(const float4*)(entity_emb + (size_t)tgt_idx * K_DIM + dof);

    float4 sv = make_float4(0.f, 0.f, 0.f, 0.f);  // sum of renormed rows
    float4 qv = make_float4(0.f, 0.f, 0.f, 0.f);  // sum of squares

    // ---- Batch A: prefetch 8 rows (indices broadcast inline) ----
    float4 va[8];
#pragma unroll
    for (int j = 0; j < 8; j++) {
        const int ia  = __shfl_sync(0xFFFFFFFFu, my_nbr, 2 * j);
        const int ib  = __shfl_sync(0xFFFFFFFFu, my_nbr, 2 * j + 1);
        const int idx = hi ? ib : ia;
        va[j] = *(const float4*)(entity_emb + (size_t)idx * K_DIM + dof);
    }

    // Target renorm chain overlaps with batch-A loads in flight
    float tp = dot4(tv);
    {
        float dm = 0.f;
        half_reduce2(tp, dm);
    }
    const float ts = renorm_scale(tp);

    fm_accum4(va + 0, sv, qv);

    // ---- Batch B: prefetch next 8 while finishing batch A ----
    float4 vb[8];
#pragma unroll
    for (int j = 0; j < 8; j++) {
        const int ia  = __shfl_sync(0xFFFFFFFFu, my_nbr, 16 + 2 * j);
        const int ib  = __shfl_sync(0xFFFFFFFFu, my_nbr, 16 + 2 * j + 1);
        const int idx = hi ? ib : ia;
        vb[j] = *(const float4*)(entity_emb + (size_t)idx * K_DIM + dof);
    }

    fm_accum4(va + 4, sv, qv);
    fm_accum4(vb + 0, sv, qv);
    fm_accum4(vb + 4, sv, qv);

    // Combine the two halves (each half saw 16 of the 32 rows).
    sv.x += __shfl_xor_sync(0xFFFFFFFFu, sv.x, 16);
    sv.y += __shfl_xor_sync(0xFFFFFFFFu, sv.y, 16);
    sv.z += __shfl_xor_sync(0xFFFFFFFFu, sv.z, 16);
    sv.w += __shfl_xor_sync(0xFFFFFFFFu, sv.w, 16);
    qv.x += __shfl_xor_sync(0xFFFFFFFFu, qv.x, 16);
    qv.y += __shfl_xor_sync(0xFFFFFFFFu, qv.y, 16);
    qv.z += __shfl_xor_sync(0xFFFFFFFFu, qv.z, 16);
    qv.w += __shfl_xor_sync(0xFFFFFFFFu, qv.w, 16);

    // att == 1 (softmax over singleton axis) => agg0 = (s^2 - q) + tgt
    float4 outv;
    outv.x = sv.x * sv.x - qv.x + tv.x * ts;
    outv.y = sv.y * sv.y - qv.y + tv.y * ts;
    outv.z = sv.z * sv.z - qv.z + tv.z * ts;
    outv.w = sv.w * sv.w - qv.w + tv.w * ts;

    if (!hi)
        *(float4*)(g_agg0 + (size_t)warp * K_DIM + dof) = outv;
}

// ---------------------------------------------------------------------------
// Hop 1 + score: one warp per b in [0, B).
//   ent1 = agg0[nbr1_idx[b,:]]  (NO renorm — these are aggregates)
//   items = fm(ent1) + renorm(entity_emb[item_ids[b]])
//   logit[b] = sigmoid( dot(renorm(user_emb[u[b]]), items) )
// ---------------------------------------------------------------------------
__global__ void __launch_bounds__(256) hop1_kernel(
    const float* __restrict__ entity_emb,
    const float* __restrict__ user_emb,
    const int*   __restrict__ u,
    const int*   __restrict__ item_ids,
    const int*   __restrict__ nbr1_idx,
    float*       __restrict__ out)
{
    const int warp = (blockIdx.x * blockDim.x + threadIdx.x) >> 5;
    const int lane = threadIdx.x & 31;
    if (warp >= B_SZ) return;

    const bool hi  = (lane >= 16);
    const int  dof = (lane & 15) * 4;

    const int my_nbr = nbr1_idx[warp * DEG + lane];
    const int it = item_ids[warp];
    const int uu = u[warp];

    // ---- Prefetch phase ----
    const float4 tv = *(const float4*)(entity_emb + (size_t)it * K_DIM + dof);
    const float4 uv = *(const float4*)(user_emb  + (size_t)uu * K_DIM + dof);

    float4 sv = make_float4(0.f, 0.f, 0.f, 0.f);
    float4 qv = make_float4(0.f, 0.f, 0.f, 0.f);

    float4 v[8];
#pragma unroll
    for (int j = 0; j < 8; j++) {
        const int ia  = __shfl_sync(0xFFFFFFFFu, my_nbr, 2 * j);
        const int ib  = __shfl_sync(0xFFFFFFFFu, my_nbr, 2 * j + 1);
        const int idx = hi ? ib : ia;
        v[j] = *(const float4*)(g_agg0 + (size_t)idx * K_DIM + dof);
    }

    float4 v2[8];
#pragma unroll
    for (int j = 0; j < 8; j++) {
        const int ia  = __shfl_sync(0xFFFFFFFFu, my_nbr, 16 + 2 * j);
        const int ib  = __shfl_sync(0xFFFFFFFFu, my_nbr, 16 + 2 * j + 1);
        const int idx = hi ? ib : ia;
        v2[j] = *(const float4*)(g_agg0 + (size_t)idx * K_DIM + dof);
    }

#pragma unroll
    for (int j = 0; j < 8; j++) {
        sv.x += v[j].x;  qv.x += v[j].x * v[j].x;
        sv.y += v[j].y;  qv.y += v[j].y * v[j].y;
        sv.z += v[j].z;  qv.z += v[j].z * v[j].z;
        sv.w += v[j].w;  qv.w += v[j].w * v[j].w;
    }
#pragma unroll
    for (int j = 0; j < 8; j++) {
        sv.x += v2[j].x;  qv.x += v2[j].x * v2[j].x;
        sv.y += v2[j].y;  qv.y += v2[j].y * v2[j].y;
        sv.z += v2[j].z;  qv.z += v2[j].z * v2[j].z;
        sv.w += v2[j].w;  qv.w += v2[j].w * v2[j].w;
    }

    // Combine halves
    sv.x += __shfl_xor_sync(0xFFFFFFFFu, sv.x, 16);
    sv.y += __shfl_xor_sync(0xFFFFFFFFu, sv.y, 16);
    sv.z += __shfl_xor_sync(0xFFFFFFFFu, sv.z, 16);
    sv.w += __shfl_xor_sync(0xFFFFFFFFu, sv.w, 16);
    qv.x += __shfl_xor_sync(0xFFFFFFFFu, qv.x, 16);
    qv.y += __shfl_xor_sync(0xFFFFFFFFu, qv.y, 16);
    qv.z += __shfl_xor_sync(0xFFFFFFFFu, qv.z, 16);
    qv.w += __shfl_xor_sync(0xFFFFFFFFu, qv.w, 16);

    // Item row + user row, renormed (both halves compute identically)
    float tp = dot4(tv);
    float up = dot4(uv);
    half_reduce2(tp, up);
    const float ts = renorm_scale(tp);
    const float us = renorm_scale(up);

    // items = fm + tgt; dot with renormed user (reduce within a half).
    float d =
        (uv.x * us) * (sv.x * sv.x - qv.x + tv.x * ts) +
        (uv.y * us) * (sv.y * sv.y - qv.y + tv.y * ts) +
        (uv.z * us) * (sv.z * sv.z - qv.z + tv.z * ts) +
        (uv.w * us) * (sv.w * sv.w - qv.w + tv.w * ts);
    float dm = 0.f;
    half_reduce2(d, dm);

    if (lane == 0)
        out[warp] = 1.0f / (1.0f + expf(-d));
}

// ---------------------------------------------------------------------------
// Launch
// Input order (metadata): 0 entity_emb, 1 user_emb, 2 Wa, 3 ba, 4 Wh, 5 bh,
//                         6 u, 7 item_ids, 8 nbr1_idx, 9 node_ids0, 10 nbr0
// Wa/ba/Wh/bh are provably dead (softmax over singleton axis == 1).
// ---------------------------------------------------------------------------
extern "C" void kernel_launch(void* const* d_in, const int* in_sizes, int n_in,
                              void* d_out, int out_size)
{
    const float* entity_emb = (const float*)d_in[0];
    const float* user_emb   = (const float*)d_in[1];
    const int*   u          = (const int*)d_in[6];
    const int*   item_ids   = (const int*)d_in[7];
    const int*   nbr1_idx   = (const int*)d_in[8];
    const int*   node_ids0  = (const int*)d_in[9];
    const int*   nbr0       = (const int*)d_in[10];
    float* out = (float*)d_out;

    // hop0: N0 warps, 4 warps per 128-thread block
    hop0_kernel<<<N0 / 4, 128>>>(entity_emb, node_ids0, nbr0);
    // hop1: B warps, 8 warps per 256-thread block
    hop1_kernel<<<B_SZ / 8, 256>>>(entity_emb, user_emb, u, item_ids, nbr1_idx, out);
}